// round 13
// baseline (speedup 1.0000x reference)
#include <cuda_runtime.h>
#include <math.h>
#include <stdint.h>

#define L_   1024
#define B_   32
#define F_   24
#define S_   12
#define NN   (L_*B_)
#define DWIN 12
#define NITER 16          // n per CTA (all share one t)
#define NPAIR (NITER/2)

// per-buffer smem layout (floats), conflict-free pitches
#define OFF_FF   0          // 24 x 28
#define OFF_SFT  672        // 12 x 28
#define OFF_FS   1008       // 24 x 20
#define OFF_FST  1488       // 24 x 20
#define OFF_SS   1968       // 12 x 20
#define OFF_F    2208       // 24
#define OFF_S    2232       // 12
#define PN       2248       // 16B-aligned per-buffer stride
#define NCHUNK   405

__device__ float g_partial[NN];

__device__ __forceinline__ uint32_t smem_u32(const void* p) {
    uint32_t a;
    asm("{ .reg .u64 t; cvta.to.shared.u64 t, %1; cvt.u32.u64 %0, t; }" : "=r"(a) : "l"(p));
    return a;
}
__device__ __forceinline__ void cp16(uint32_t dst, const float4* src) {
    asm volatile("cp.async.cg.shared.global [%0], [%1], 16;" :: "r"(dst), "l"(src) : "memory");
}
__device__ __forceinline__ void cp_commit() {
    asm volatile("cp.async.commit_group;" ::: "memory");
}
template <int N>
__device__ __forceinline__ void cp_wait() {
    asm volatile("cp.async.wait_group %0;" :: "n"(N) : "memory");
}

__device__ __forceinline__ float warp_max_red(float v) {
    #pragma unroll
    for (int o = 16; o; o >>= 1) v = fmaxf(v, __shfl_xor_sync(0xffffffffu, v, o));
    return v;
}
__device__ __forceinline__ float warp_sum_red(float v) {
    #pragma unroll
    for (int o = 16; o; o >>= 1) v += __shfl_xor_sync(0xffffffffu, v, o);
    return v;
}

// ---------------------------------------------------------------------------
// Fused kernel: 16 n per CTA (one t). Inline message stencil (smem-resident),
// 2 n per iteration, 4-buffer cp.async pipeline, 8 barriers per CTA.
// ---------------------------------------------------------------------------
struct Chunk { const float4* src; int stride; int dst; };

__device__ __forceinline__ Chunk make_chunk(
    int q, int n0,
    const float* f, const float* s, const float* fs, const float* ff,
    const float* ss, const float* fst, const float* sft)
{
    Chunk c;
    if (q < 144) {
        int j = q;
        c.src = (const float4*)ff + (long)n0 * 144 + j; c.stride = 144;
        c.dst = OFF_FF + (j / 6) * 28 + (j % 6) * 4;
    } else if (q < 216) {
        int j = q - 144;
        c.src = (const float4*)fs + (long)n0 * 72 + j; c.stride = 72;
        c.dst = OFF_FS + (j / 3) * 20 + (j % 3) * 4;
    } else if (q < 288) {
        int j = q - 216;
        c.src = (const float4*)fst + (long)n0 * 72 + j; c.stride = 72;
        c.dst = OFF_FST + (j / 3) * 20 + (j % 3) * 4;
    } else if (q < 360) {
        int j = q - 288;
        c.src = (const float4*)sft + (long)n0 * 72 + j; c.stride = 72;
        c.dst = OFF_SFT + (j / 6) * 28 + (j % 6) * 4;
    } else if (q < 396) {
        int j = q - 360;
        c.src = (const float4*)ss + (long)n0 * 36 + j; c.stride = 36;
        c.dst = OFF_SS + (j / 3) * 20 + (j % 3) * 4;
    } else if (q < 402) {
        int j = q - 396;
        c.src = (const float4*)f + (long)n0 * 6 + j; c.stride = 6;
        c.dst = OFF_F + j * 4;
    } else {
        int j = q - 402;
        c.src = (const float4*)s + (long)n0 * 3 + j; c.stride = 3;
        c.dst = OFF_S + j * 4;
    }
    return c;
}

__global__ __launch_bounds__(128)
void tf_main(const float* __restrict__ f, const float* __restrict__ s,
             const float* __restrict__ fs, const float* __restrict__ ff,
             const float* __restrict__ ss, const float* __restrict__ fst,
             const float* __restrict__ sft,
             const int* __restrict__ fl_g, const int* __restrict__ sl_g,
             const int* __restrict__ yl_g,
             const int* __restrict__ y2f, const int* __restrict__ y2s,
             float* __restrict__ out_f, float* __restrict__ out_s)
{
    const int n0  = blockIdx.x * NITER;
    const int tid = threadIdx.x;
    const int lane = tid & 31;
    const int wid = tid >> 5;
    const int sub = wid >> 1;        // 0: n_a, 1: n_b
    const bool isF = !(wid & 1);     // warps 0,2: F-work; 1,3: S-work

    __shared__ __align__(16) float sm[4 * PN];
    __shared__ __align__(16) float s_msg[NITER * 72];
    __shared__ float s_sc[2][2][6];

    const uint32_t smb = smem_u32(sm);

    Chunk c0 = make_chunk(tid,       n0, f, s, fs, ff, ss, fst, sft);
    Chunk c1 = make_chunk(tid + 128, n0, f, s, fs, ff, ss, fst, sft);
    Chunk c2 = make_chunk(tid + 256, n0, f, s, fs, ff, ss, fst, sft);
    const bool has3 = (tid + 384) < NCHUNK;   // 21 threads
    Chunk c3 = make_chunk(has3 ? tid + 384 : 0, n0, f, s, fs, ff, ss, fst, sft);

    // prologue: pair 0 -> buffers {0,1}, pair 1 -> buffers {2,3}
    #pragma unroll
    for (int p = 0; p < 2; p++) {
        #pragma unroll
        for (int u = 0; u < 2; u++) {
            const uint32_t nb = smb + (uint32_t)((p * 2 + u) * PN) * 4;
            cp16(nb + (uint32_t)c0.dst * 4, c0.src); c0.src += c0.stride;
            cp16(nb + (uint32_t)c1.dst * 4, c1.src); c1.src += c1.stride;
            cp16(nb + (uint32_t)c2.dst * 4, c2.src); c2.src += c2.stride;
            if (has3) { cp16(nb + (uint32_t)c3.dst * 4, c3.src); c3.src += c3.stride; }
        }
        cp_commit();
    }

    // ---- inline message stencil: 16 n x 18 float4-groups, all share t ----
    {
        const float wt[DWIN + 1] = {
            1.0f, 0.88249690258f, 0.60653065971f, 0.32465246735f, 0.13533528324f,
            0.04393693362f, 0.01110899654f, 0.00218749112f, 3.35462628e-4f,
            4.00652974e-5f, 3.72665317e-6f, 2.69957850e-7f, 1.52299797e-8f };
        const int t = n0 / B_;
        const bool interior = (t >= DWIN) && (t <= (L_ - 1) - DWIN);
        const float rsp = __frcp_rn(fmaxf((float)t, 1.0f));
        const float rsf = __frcp_rn(fmaxf((float)((L_ - 1) - t), 1.0f));
        const int dmax_p = min(DWIN, t);
        const int dmax_f = min(DWIN, (L_ - 1) - t);

        #pragma unroll
        for (int o = tid; o < NITER * 18; o += 128) {
            const int nl = o / 18;
            const int r  = o - nl * 18;
            const int n  = n0 + nl;
            const float* src; int C; int ch; bool past;
            if      (r < 6)  { src = f; C = F_; ch = r * 4;          past = true;  }
            else if (r < 12) { src = f; C = F_; ch = r * 4 - 24;     past = false; }
            else if (r < 15) { src = s; C = S_; ch = (r - 12) * 4;   past = true;  }
            else             { src = s; C = S_; ch = (r - 15) * 4;   past = false; }
            const long stride = (long)B_ * C;
            const float* base = src + (long)n * C + ch;
            float4 a = make_float4(0.f, 0.f, 0.f, 0.f);
            if (interior) {
                #pragma unroll
                for (int d = 1; d <= DWIN; d++) {
                    float4 v = *(const float4*)(past ? (base - d * stride) : (base + d * stride));
                    a.x += wt[d]*v.x; a.y += wt[d]*v.y; a.z += wt[d]*v.z; a.w += wt[d]*v.w;
                }
            } else {
                const int dmax = past ? dmax_p : dmax_f;
                #pragma unroll
                for (int d = 1; d <= DWIN; d++) {
                    if (d <= dmax) {
                        float4 v = *(const float4*)(past ? (base - d * stride) : (base + d * stride));
                        a.x += wt[d]*v.x; a.y += wt[d]*v.y; a.z += wt[d]*v.z; a.w += wt[d]*v.w;
                    }
                }
            }
            const float sc = past ? rsp : rsf;
            a.x *= sc; a.y *= sc; a.z *= sc; a.w *= sc;
            *(float4*)(s_msg + nl * 72 + r * 4) = a;
        }
    }

    for (int ip = 0; ip < NPAIR; ip++) {
        const int set = (ip & 1) * 2;
        const int n = n0 + 2 * ip + sub;
        const float* base = sm + (set + sub) * PN;
        const float* msg  = s_msg + (2 * ip + sub) * 72;

        int lab = 0, yidx = 0;
        if (lane == 0) {
            if (isF) { lab = fl_g[n]; yidx = y2f[yl_g[n]]; }
            else     { lab = sl_g[n]; yidx = y2s[yl_g[n]]; }
        }

        if (ip == 0) cp_wait<1>(); else cp_wait<0>();
        __syncthreads();
        // barrier also publishes s_msg (ip==0) and frees pair ip-1's set (ip>0)

        if (ip >= 1 && ip + 1 < NPAIR) {
            const int pset = ((ip + 1) & 1) * 2;
            #pragma unroll
            for (int u = 0; u < 2; u++) {
                const uint32_t nb = smb + (uint32_t)((pset + u) * PN) * 4;
                cp16(nb + (uint32_t)c0.dst * 4, c0.src); c0.src += c0.stride;
                cp16(nb + (uint32_t)c1.dst * 4, c1.src); c1.src += c1.stride;
                cp16(nb + (uint32_t)c2.dst * 4, c2.src); c2.src += c2.stride;
                if (has3) { cp16(nb + (uint32_t)c3.dst * 4, c3.src); c3.src += c3.stride; }
            }
            cp_commit();
        }

        // deferred loss writes for pair ip-1
        if (ip > 0 && lane == 0 && wid < 2) {
            const float* sc = s_sc[(ip - 1) & 1][wid];
            g_partial[n0 + 2 * (ip - 1) + wid] =
                -(sc[0] + sc[1] + sc[2] + sc[3]) - sc[4] * sc[5];
        }

        const float* fmp = msg;
        const float* fmf = msg + 24;
        const float* smp = msg + 48;
        const float* smf = msg + 60;
        const int lab_b  = __shfl_sync(0xffffffffu, lab, 0);
        const int yidx_b = __shfl_sync(0xffffffffu, yidx, 0);
        float* sc = s_sc[ip & 1][sub];

        if (isF) {
            float nf = -INFINITY, xf = -INFINITY;
            if (lane < F_) {
                const int g = lane;
                float4 ffr[6], fstr[3], fsr[3];
                #pragma unroll
                for (int j = 0; j < 6; j++) ffr[j]  = *(const float4*)(base + OFF_FF  + g*28 + 4*j);
                #pragma unroll
                for (int j = 0; j < 3; j++) fstr[j] = *(const float4*)(base + OFF_FST + g*20 + 4*j);
                #pragma unroll
                for (int j = 0; j < 3; j++) fsr[j]  = *(const float4*)(base + OFF_FS  + g*20 + 4*j);
                float a1 = 0.f, a2 = 0.f, a3 = 0.f, a4 = 0.f, a5 = 0.f;
                #pragma unroll
                for (int k = 0; k < F_; k++) a1 += fmp[k] * base[OFF_FF + k*28 + g];
                #pragma unroll
                for (int k = 0; k < F_; k++) a2 += ((const float*)ffr)[k] * fmf[k];
                #pragma unroll
                for (int k = 0; k < S_; k++) a3 += smp[k] * base[OFF_SFT + k*28 + g];
                #pragma unroll
                for (int k = 0; k < S_; k++) a4 += ((const float*)fstr)[k] * smf[k];
                #pragma unroll
                for (int k = 0; k < S_; k++) a5 += ((const float*)fsr)[k] * base[OFF_S + k];
                xf = base[OFF_F + g];
                nf = xf + 0.5f * (((a1 + a2) + (a3 + a4)) + a5);
            }
            float m2 = warp_max_red(nf);
            float e2 = (lane < F_) ? __expf(nf - m2) : 0.0f;
            float z2 = warp_sum_red(e2);
            if (lane < F_) out_f[(long)n * F_ + lane] = e2 * __frcp_rn(z2);
            float m0 = warp_max_red(xf);
            float e0 = (lane < F_) ? __expf(xf - m0) : 0.0f;
            float z0 = warp_sum_red(e0);
            float nf_l = __shfl_sync(0xffffffffu, nf, lab_b);
            float xf_l = __shfl_sync(0xffffffffu, xf, lab_b);
            float pf_y = __shfl_sync(0xffffffffu, e0, yidx_b) * __frcp_rn(z0);
            if (lane == 0) {
                sc[0] = nf_l - (m2 + __logf(z2));
                sc[2] = xf_l - (m0 + __logf(z0));
                sc[4] = pf_y;
            }
        } else {
            float ns = -INFINITY, xs = -INFINITY;
            if (lane < S_) {
                const int u = lane;
                float4 ssr[3], sftr[6];
                #pragma unroll
                for (int j = 0; j < 3; j++) ssr[j]  = *(const float4*)(base + OFF_SS  + u*20 + 4*j);
                #pragma unroll
                for (int j = 0; j < 6; j++) sftr[j] = *(const float4*)(base + OFF_SFT + u*28 + 4*j);
                float a1 = 0.f, a2 = 0.f, a3 = 0.f, a4 = 0.f, a5 = 0.f;
                #pragma unroll
                for (int k = 0; k < S_; k++) a1 += smp[k] * base[OFF_SS + k*20 + u];
                #pragma unroll
                for (int k = 0; k < S_; k++) a2 += ((const float*)ssr)[k] * smf[k];
                #pragma unroll
                for (int k = 0; k < F_; k++) a3 += fmp[k] * base[OFF_FST + k*20 + u];
                #pragma unroll
                for (int k = 0; k < F_; k++) a4 += ((const float*)sftr)[k] * fmf[k];
                #pragma unroll
                for (int k = 0; k < F_; k++) a5 += base[OFF_F + k] * base[OFF_FS + k*20 + u];
                xs = base[OFF_S + u];
                ns = xs + 0.5f * (((a1 + a2) + (a3 + a4)) + a5);
            }
            float m3 = warp_max_red(ns);
            float e3 = (lane < S_) ? __expf(ns - m3) : 0.0f;
            float z3 = warp_sum_red(e3);
            if (lane < S_) out_s[(long)n * S_ + lane] = e3 * __frcp_rn(z3);
            float m1 = warp_max_red(xs);
            float e1 = (lane < S_) ? __expf(xs - m1) : 0.0f;
            float z1 = warp_sum_red(e1);
            float ns_l = __shfl_sync(0xffffffffu, ns, lab_b);
            float xs_l = __shfl_sync(0xffffffffu, xs, lab_b);
            float ps_y = __shfl_sync(0xffffffffu, e1, yidx_b) * __frcp_rn(z1);
            if (lane == 0) {
                sc[1] = ns_l - (m3 + __logf(z3));
                sc[3] = xs_l - (m1 + __logf(z1));
                sc[5] = ps_y;
            }
        }
    }
    __syncthreads();
    if (lane == 0 && wid < 2) {
        const float* sc = s_sc[(NPAIR - 1) & 1][wid];
        g_partial[n0 + 2 * (NPAIR - 1) + wid] =
            -(sc[0] + sc[1] + sc[2] + sc[3]) - sc[4] * sc[5];
    }
}

// ---------------------------------------------------------------------------
// deterministic mean of g_partial
// ---------------------------------------------------------------------------
__global__ __launch_bounds__(1024)
void tf_reduce(float* __restrict__ out_loss)
{
    __shared__ float sh[1024];
    const int tid = threadIdx.x;
    const float4* gp = (const float4*)g_partial;
    float a = 0.0f;
    #pragma unroll
    for (int i = 0; i < 8; i++) {
        float4 v = gp[tid + i * 1024];
        a += (v.x + v.y) + (v.z + v.w);
    }
    sh[tid] = a;
    __syncthreads();
    #pragma unroll
    for (int st = 512; st; st >>= 1) {
        if (tid < st) sh[tid] += sh[tid + st];
        __syncthreads();
    }
    if (tid == 0) *out_loss = sh[0] * (1.0f / (float)NN);
}

extern "C" void kernel_launch(void* const* d_in, const int* in_sizes, int n_in,
                              void* d_out, int out_size)
{
    const float* f   = (const float*)d_in[0];
    const float* s   = (const float*)d_in[1];
    const float* fs  = (const float*)d_in[2];
    const float* ff  = (const float*)d_in[3];
    const float* ss  = (const float*)d_in[4];
    const float* fst = (const float*)d_in[5];
    const float* sft = (const float*)d_in[6];
    const int*   fl  = (const int*)d_in[7];
    const int*   sl  = (const int*)d_in[8];
    const int*   yl  = (const int*)d_in[9];
    // d_in[10] = mask: all-true by construction; terms reduce to plain means.
    const int*   y2f = (const int*)d_in[11];
    const int*   y2s = (const int*)d_in[12];

    float* out   = (float*)d_out;
    float* out_f = out;
    float* out_s = out + (long)NN * F_;
    float* out_l = out + (long)NN * (F_ + S_);

    tf_main<<<NN / NITER, 128>>>(f, s, fs, ff, ss, fst, sft, fl, sl, yl, y2f, y2s, out_f, out_s);
    tf_reduce<<<1, 1024>>>(out_l);
}

// round 14
// speedup vs baseline: 1.0963x; 1.0963x over previous
#include <cuda_runtime.h>
#include <math.h>
#include <stdint.h>

#define L_   1024
#define B_   32
#define F_   24
#define S_   12
#define NN   (L_*B_)
#define DWIN 12
#define MSGC 72
#define NITER 16
#define NSTAGE 3
#define NBLK  (NN / NITER)   // 2048 tf_main CTAs

// per-buffer smem layout (floats), 16B-aligned conflict-free pitches
#define OFF_FF   0          // 24 x 28
#define OFF_SFT  672        // 12 x 28
#define OFF_FS   1008       // 24 x 20
#define OFF_FST  1488       // 24 x 20
#define OFF_SS   1968       // 12 x 20
#define OFF_MSG  2208       // 72
#define OFF_F    2280       // 24
#define OFF_S    2304       // 12 (+4 pad)
#define PN       2320
#define NCHUNK   423

__device__ float g_partial[NBLK];
__device__ __align__(16) float g_msg[NN * MSGC];

__device__ __forceinline__ uint32_t smem_u32(const void* p) {
    uint32_t a;
    asm("{ .reg .u64 t; cvta.to.shared.u64 t, %1; cvt.u32.u64 %0, t; }" : "=r"(a) : "l"(p));
    return a;
}
__device__ __forceinline__ void cp16(uint32_t dst, const float4* src) {
    asm volatile("cp.async.cg.shared.global [%0], [%1], 16;" :: "r"(dst), "l"(src) : "memory");
}
__device__ __forceinline__ void cp_commit() {
    asm volatile("cp.async.commit_group;" ::: "memory");
}
template <int N>
__device__ __forceinline__ void cp_wait() {
    asm volatile("cp.async.wait_group %0;" :: "n"(N) : "memory");
}

__device__ __forceinline__ float warp_max_red(float v) {
    #pragma unroll
    for (int o = 16; o; o >>= 1) v = fmaxf(v, __shfl_xor_sync(0xffffffffu, v, o));
    return v;
}
__device__ __forceinline__ float warp_sum_red(float v) {
    #pragma unroll
    for (int o = 16; o; o >>= 1) v += __shfl_xor_sync(0xffffffffu, v, o);
    return v;
}

// ---------------------------------------------------------------------------
// Kernel 1: temporal messages, 4-t chunk per thread (15 loads -> 4 outputs).
// thread = (tg, b, r): tg = t/4 block, r = float4 channel group (18 total).
// ---------------------------------------------------------------------------
__global__ __launch_bounds__(256)
void tf_msg(const float* __restrict__ f, const float* __restrict__ s)
{
    const float wt[DWIN + 1] = {
        1.0f, 0.88249690258f, 0.60653065971f, 0.32465246735f, 0.13533528324f,
        0.04393693362f, 0.01110899654f, 0.00218749112f, 3.35462628e-4f,
        4.00652974e-5f, 3.72665317e-6f, 2.69957850e-7f, 1.52299797e-8f };

    const int idx   = blockIdx.x * 256 + threadIdx.x;   // < (NN/4)*18
    const int group = idx / 18;                          // (tg, b)
    const int r     = idx - group * 18;
    const int tg    = group >> 5;
    const int b     = group & 31;
    const int t0    = 4 * tg;
    const int n0    = t0 * B_ + b;

    const float* src; int C; int ch; bool past;
    if      (r < 6)  { src = f; C = F_; ch = r * 4;          past = true;  }
    else if (r < 12) { src = f; C = F_; ch = r * 4 - 24;     past = false; }
    else if (r < 15) { src = s; C = S_; ch = (r - 12) * 4;   past = true;  }
    else             { src = s; C = S_; ch = (r - 15) * 4;   past = false; }

    const long stride = (long)B_ * C;
    const float* base = src + (long)n0 * C + ch;    // element (t0, b, ch)

    float4 acc[4];
    #pragma unroll
    for (int q = 0; q < 4; q++) acc[q] = make_float4(0.f, 0.f, 0.f, 0.f);

    if (past) {
        // loads j = -12..2 ; output q gets wt[q-j] for 1 <= q-j <= 12
        const bool fast = (t0 >= DWIN);
        #pragma unroll
        for (int j = -DWIN; j <= 2; j++) {
            if (fast || t0 + j >= 0) {
                float4 v = *(const float4*)(base + (long)j * stride);
                #pragma unroll
                for (int q = 0; q < 4; q++) {
                    const int d = q - j;
                    if (d >= 1 && d <= DWIN) {
                        acc[q].x += wt[d]*v.x; acc[q].y += wt[d]*v.y;
                        acc[q].z += wt[d]*v.z; acc[q].w += wt[d]*v.w;
                    }
                }
            }
        }
        #pragma unroll
        for (int q = 0; q < 4; q++) {
            const float sc = __frcp_rn(fmaxf((float)(t0 + q), 1.0f));
            acc[q].x *= sc; acc[q].y *= sc; acc[q].z *= sc; acc[q].w *= sc;
        }
    } else {
        // loads j = 1..15 ; output q gets wt[j-q] for 1 <= j-q <= 12
        const bool fast = (t0 + 15 <= L_ - 1);
        #pragma unroll
        for (int j = 1; j <= 15; j++) {
            if (fast || t0 + j <= L_ - 1) {
                float4 v = *(const float4*)(base + (long)j * stride);
                #pragma unroll
                for (int q = 0; q < 4; q++) {
                    const int d = j - q;
                    if (d >= 1 && d <= DWIN) {
                        acc[q].x += wt[d]*v.x; acc[q].y += wt[d]*v.y;
                        acc[q].z += wt[d]*v.z; acc[q].w += wt[d]*v.w;
                    }
                }
            }
        }
        #pragma unroll
        for (int q = 0; q < 4; q++) {
            const float sc = __frcp_rn(fmaxf((float)((L_ - 1) - (t0 + q)), 1.0f));
            acc[q].x *= sc; acc[q].y *= sc; acc[q].z *= sc; acc[q].w *= sc;
        }
    }
    #pragma unroll
    for (int q = 0; q < 4; q++)
        *(float4*)(g_msg + (long)(n0 + q * B_) * MSGC + r * 4) = acc[q];
}

// ---------------------------------------------------------------------------
// Kernel 2: R9 skeleton — 16 n per CTA, 3-stage cp.async pipeline, prefetch
// after barrier; loss partials accumulated in thread 0, one write per CTA.
// ---------------------------------------------------------------------------
struct Chunk { const float4* src; int stride; int dst; };

__device__ __forceinline__ Chunk make_chunk(
    int q, int n0,
    const float* f, const float* s, const float* fs, const float* ff,
    const float* ss, const float* fst, const float* sft)
{
    Chunk c;
    if (q < 144) {
        int j = q;
        c.src = (const float4*)ff + (long)n0 * 144 + j; c.stride = 144;
        c.dst = OFF_FF + (j / 6) * 28 + (j % 6) * 4;
    } else if (q < 216) {
        int j = q - 144;
        c.src = (const float4*)fs + (long)n0 * 72 + j; c.stride = 72;
        c.dst = OFF_FS + (j / 3) * 20 + (j % 3) * 4;
    } else if (q < 288) {
        int j = q - 216;
        c.src = (const float4*)fst + (long)n0 * 72 + j; c.stride = 72;
        c.dst = OFF_FST + (j / 3) * 20 + (j % 3) * 4;
    } else if (q < 360) {
        int j = q - 288;
        c.src = (const float4*)sft + (long)n0 * 72 + j; c.stride = 72;
        c.dst = OFF_SFT + (j / 6) * 28 + (j % 6) * 4;
    } else if (q < 396) {
        int j = q - 360;
        c.src = (const float4*)ss + (long)n0 * 36 + j; c.stride = 36;
        c.dst = OFF_SS + (j / 3) * 20 + (j % 3) * 4;
    } else if (q < 414) {
        int j = q - 396;
        c.src = (const float4*)g_msg + (long)n0 * 18 + j; c.stride = 18;
        c.dst = OFF_MSG + j * 4;
    } else if (q < 420) {
        int j = q - 414;
        c.src = (const float4*)f + (long)n0 * 6 + j; c.stride = 6;
        c.dst = OFF_F + j * 4;
    } else {
        int j = q - 420;
        c.src = (const float4*)s + (long)n0 * 3 + j; c.stride = 3;
        c.dst = OFF_S + j * 4;
    }
    return c;
}

__global__ __launch_bounds__(128)
void tf_main(const float* __restrict__ f, const float* __restrict__ s,
             const float* __restrict__ fs, const float* __restrict__ ff,
             const float* __restrict__ ss, const float* __restrict__ fst,
             const float* __restrict__ sft,
             const int* __restrict__ fl_g, const int* __restrict__ sl_g,
             const int* __restrict__ yl_g,
             const int* __restrict__ y2f, const int* __restrict__ y2s,
             float* __restrict__ out_f, float* __restrict__ out_s)
{
    const int n0  = blockIdx.x * NITER;
    const int tid = threadIdx.x;
    const int lane = tid & 31;
    const int wid = tid >> 5;

    __shared__ __align__(16) float sm[NSTAGE * PN];
    __shared__ float s_sc[2][6];

    const uint32_t smb = smem_u32(sm);

    Chunk c0 = make_chunk(tid,       n0, f, s, fs, ff, ss, fst, sft);
    Chunk c1 = make_chunk(tid + 128, n0, f, s, fs, ff, ss, fst, sft);
    Chunk c2 = make_chunk(tid + 256, n0, f, s, fs, ff, ss, fst, sft);
    const bool has3 = (tid + 384) < NCHUNK;
    Chunk c3 = make_chunk(has3 ? tid + 384 : 0, n0, f, s, fs, ff, ss, fst, sft);

    // prefetch iterations 0 and 1 into buffers 0 and 1
    #pragma unroll
    for (int p = 0; p < 2; p++) {
        const uint32_t nb = smb + (uint32_t)(p * PN) * 4;
        cp16(nb + (uint32_t)c0.dst * 4, c0.src); c0.src += c0.stride;
        cp16(nb + (uint32_t)c1.dst * 4, c1.src); c1.src += c1.stride;
        cp16(nb + (uint32_t)c2.dst * 4, c2.src); c2.src += c2.stride;
        if (has3) { cp16(nb + (uint32_t)c3.dst * 4, c3.src); c3.src += c3.stride; }
        cp_commit();
    }

    float loss_acc = 0.0f;      // thread 0 only
    int bi = 0;
    int pi = 2;
    for (int i = 0; i < NITER; i++) {
        const int n = n0 + i;
        const float* base = sm + bi * PN;

        int lab = 0, yidx = 0;
        if (lane == 0) {
            if (wid == 0)      { lab = fl_g[n]; }
            else if (wid == 1) { lab = sl_g[n]; }
            else if (wid == 2) { lab = fl_g[n]; yidx = y2f[yl_g[n]]; }
            else               { lab = sl_g[n]; yidx = y2s[yl_g[n]]; }
        }

        if (i + 1 < NITER) cp_wait<1>(); else cp_wait<0>();
        __syncthreads();
        // all warps past epilogue i-1 -> overwriting buffer pi is race-free

        if (i + 2 < NITER) {
            const uint32_t nb = smb + (uint32_t)(pi * PN) * 4;
            cp16(nb + (uint32_t)c0.dst * 4, c0.src); c0.src += c0.stride;
            cp16(nb + (uint32_t)c1.dst * 4, c1.src); c1.src += c1.stride;
            cp16(nb + (uint32_t)c2.dst * 4, c2.src); c2.src += c2.stride;
            if (has3) { cp16(nb + (uint32_t)c3.dst * 4, c3.src); c3.src += c3.stride; }
            cp_commit();
        }

        // deferred loss combine for iteration i-1 (accumulated, not stored)
        if (tid == 0 && i > 0) {
            const float* sc = s_sc[(i - 1) & 1];
            loss_acc += -(sc[0] + sc[1] + sc[2] + sc[3]) - sc[4] * sc[5];
        }

        const float* fmp = base + OFF_MSG;
        const float* fmf = base + OFF_MSG + 24;
        const float* smp = base + OFF_MSG + 48;
        const float* smf = base + OFF_MSG + 60;
        const int lab_b  = __shfl_sync(0xffffffffu, lab, 0);
        const int yidx_b = __shfl_sync(0xffffffffu, yidx, 0);
        float* sc = s_sc[i & 1];

        if (wid == 0) {
            float nf = -INFINITY;
            if (lane < F_) {
                const int g = lane;
                float4 ffr[6], fstr[3], fsr[3];
                #pragma unroll
                for (int j = 0; j < 6; j++) ffr[j]  = *(const float4*)(base + OFF_FF  + g*28 + 4*j);
                #pragma unroll
                for (int j = 0; j < 3; j++) fstr[j] = *(const float4*)(base + OFF_FST + g*20 + 4*j);
                #pragma unroll
                for (int j = 0; j < 3; j++) fsr[j]  = *(const float4*)(base + OFF_FS  + g*20 + 4*j);
                float a1 = 0.f, a2 = 0.f, a3 = 0.f, a4 = 0.f, a5 = 0.f;
                #pragma unroll
                for (int k = 0; k < F_; k++) a1 += fmp[k] * base[OFF_FF + k*28 + g];
                #pragma unroll
                for (int k = 0; k < F_; k++) a2 += ((const float*)ffr)[k] * fmf[k];
                #pragma unroll
                for (int k = 0; k < S_; k++) a3 += smp[k] * base[OFF_SFT + k*28 + g];
                #pragma unroll
                for (int k = 0; k < S_; k++) a4 += ((const float*)fstr)[k] * smf[k];
                #pragma unroll
                for (int k = 0; k < S_; k++) a5 += ((const float*)fsr)[k] * base[OFF_S + k];
                nf = base[OFF_F + g] + 0.5f * (((a1 + a2) + (a3 + a4)) + a5);
            }
            float m = warp_max_red(nf);
            float e = (lane < F_) ? __expf(nf - m) : 0.0f;
            float z = warp_sum_red(e);
            float rz = __frcp_rn(z);
            if (lane < F_) out_f[(long)n * F_ + lane] = e * rz;
            float nf_l = __shfl_sync(0xffffffffu, nf, lab_b);
            if (lane == 0) sc[0] = nf_l - (m + __logf(z));
        } else if (wid == 1) {
            float ns = -INFINITY;
            if (lane < S_) {
                const int u = lane;
                float4 ssr[3], sftr[6];
                #pragma unroll
                for (int j = 0; j < 3; j++) ssr[j]  = *(const float4*)(base + OFF_SS  + u*20 + 4*j);
                #pragma unroll
                for (int j = 0; j < 6; j++) sftr[j] = *(const float4*)(base + OFF_SFT + u*28 + 4*j);
                float a1 = 0.f, a2 = 0.f, a3 = 0.f, a4 = 0.f, a5 = 0.f;
                #pragma unroll
                for (int k = 0; k < S_; k++) a1 += smp[k] * base[OFF_SS + k*20 + u];
                #pragma unroll
                for (int k = 0; k < S_; k++) a2 += ((const float*)ssr)[k] * smf[k];
                #pragma unroll
                for (int k = 0; k < F_; k++) a3 += fmp[k] * base[OFF_FST + k*20 + u];
                #pragma unroll
                for (int k = 0; k < F_; k++) a4 += ((const float*)sftr)[k] * fmf[k];
                #pragma unroll
                for (int k = 0; k < F_; k++) a5 += base[OFF_F + k] * base[OFF_FS + k*20 + u];
                ns = base[OFF_S + u] + 0.5f * (((a1 + a2) + (a3 + a4)) + a5);
            }
            float m = warp_max_red(ns);
            float e = (lane < S_) ? __expf(ns - m) : 0.0f;
            float z = warp_sum_red(e);
            float rz = __frcp_rn(z);
            if (lane < S_) out_s[(long)n * S_ + lane] = e * rz;
            float ns_l = __shfl_sync(0xffffffffu, ns, lab_b);
            if (lane == 0) sc[1] = ns_l - (m + __logf(z));
        } else if (wid == 2) {
            float xf = (lane < F_) ? base[OFF_F + lane] : -INFINITY;
            float m = warp_max_red(xf);
            float e = (lane < F_) ? __expf(xf - m) : 0.0f;
            float z = warp_sum_red(e);
            float xf_l = __shfl_sync(0xffffffffu, xf, lab_b);
            float pf_y = __shfl_sync(0xffffffffu, e, yidx_b) * __frcp_rn(z);
            if (lane == 0) { sc[2] = xf_l - (m + __logf(z)); sc[4] = pf_y; }
        } else {
            float xs = (lane < S_) ? base[OFF_S + lane] : -INFINITY;
            float m = warp_max_red(xs);
            float e = (lane < S_) ? __expf(xs - m) : 0.0f;
            float z = warp_sum_red(e);
            float xs_l = __shfl_sync(0xffffffffu, xs, lab_b);
            float ps_y = __shfl_sync(0xffffffffu, e, yidx_b) * __frcp_rn(z);
            if (lane == 0) { sc[3] = xs_l - (m + __logf(z)); sc[5] = ps_y; }
        }

        bi = (bi == NSTAGE - 1) ? 0 : bi + 1;
        pi = (pi == NSTAGE - 1) ? 0 : pi + 1;
    }
    __syncthreads();
    if (tid == 0) {
        const float* sc = s_sc[(NITER - 1) & 1];
        loss_acc += -(sc[0] + sc[1] + sc[2] + sc[3]) - sc[4] * sc[5];
        g_partial[blockIdx.x] = loss_acc;
    }
}

// ---------------------------------------------------------------------------
// Kernel 3: deterministic mean of 2048 per-CTA partials.
// ---------------------------------------------------------------------------
__global__ __launch_bounds__(512)
void tf_reduce(float* __restrict__ out_loss)
{
    __shared__ float sh[512];
    const int tid = threadIdx.x;
    const float4* gp = (const float4*)g_partial;    // 512 float4
    float4 v = gp[tid];
    sh[tid] = (v.x + v.y) + (v.z + v.w);
    __syncthreads();
    #pragma unroll
    for (int st = 256; st; st >>= 1) {
        if (tid < st) sh[tid] += sh[tid + st];
        __syncthreads();
    }
    if (tid == 0) *out_loss = sh[0] * (1.0f / (float)NN);
}

extern "C" void kernel_launch(void* const* d_in, const int* in_sizes, int n_in,
                              void* d_out, int out_size)
{
    const float* f   = (const float*)d_in[0];
    const float* s   = (const float*)d_in[1];
    const float* fs  = (const float*)d_in[2];
    const float* ff  = (const float*)d_in[3];
    const float* ss  = (const float*)d_in[4];
    const float* fst = (const float*)d_in[5];
    const float* sft = (const float*)d_in[6];
    const int*   fl  = (const int*)d_in[7];
    const int*   sl  = (const int*)d_in[8];
    const int*   yl  = (const int*)d_in[9];
    // d_in[10] = mask: all-true by construction; terms reduce to plain means.
    const int*   y2f = (const int*)d_in[11];
    const int*   y2s = (const int*)d_in[12];

    float* out   = (float*)d_out;
    float* out_f = out;
    float* out_s = out + (long)NN * F_;
    float* out_l = out + (long)NN * (F_ + S_);

    tf_msg <<<(NN / 4) * 18 / 256, 256>>>(f, s);
    tf_main<<<NBLK, 128>>>(f, s, fs, ff, ss, fst, sft, fl, sl, yl, y2f, y2s, out_f, out_s);
    tf_reduce<<<1, 512>>>(out_l);
}

// round 15
// speedup vs baseline: 1.1488x; 1.0479x over previous
#include <cuda_runtime.h>
#include <math.h>
#include <stdint.h>

#define L_   1024
#define B_   32
#define F_   24
#define S_   12
#define NN   (L_*B_)
#define DWIN 12
#define MSGC 72
#define NITER 16
#define NSTAGE 3
#define NBLK  (NN / NITER)   // 2048 tf_main CTAs

// per-buffer smem layout (floats), 16B-aligned conflict-free pitches
#define OFF_FF   0          // 24 x 28
#define OFF_SFT  672        // 12 x 28
#define OFF_FS   1008       // 24 x 20
#define OFF_FST  1488       // 24 x 20
#define OFF_SS   1968       // 12 x 20
#define OFF_MSG  2208       // 72
#define OFF_F    2280       // 24
#define OFF_S    2304       // 12 (+4 pad)
#define PN       2320
#define NCHUNK   423

__device__ float g_partial[NBLK];
__device__ unsigned int g_done;     // zero-initialized; reset by last CTA
__device__ __align__(16) float g_msg[NN * MSGC];

__device__ __forceinline__ uint32_t smem_u32(const void* p) {
    uint32_t a;
    asm("{ .reg .u64 t; cvta.to.shared.u64 t, %1; cvt.u32.u64 %0, t; }" : "=r"(a) : "l"(p));
    return a;
}
__device__ __forceinline__ void cp16(uint32_t dst, const float4* src) {
    asm volatile("cp.async.cg.shared.global [%0], [%1], 16;" :: "r"(dst), "l"(src) : "memory");
}
__device__ __forceinline__ void cp_commit() {
    asm volatile("cp.async.commit_group;" ::: "memory");
}
template <int N>
__device__ __forceinline__ void cp_wait() {
    asm volatile("cp.async.wait_group %0;" :: "n"(N) : "memory");
}

__device__ __forceinline__ float warp_max_red(float v) {
    #pragma unroll
    for (int o = 16; o; o >>= 1) v = fmaxf(v, __shfl_xor_sync(0xffffffffu, v, o));
    return v;
}
__device__ __forceinline__ float warp_sum_red(float v) {
    #pragma unroll
    for (int o = 16; o; o >>= 1) v += __shfl_xor_sync(0xffffffffu, v, o);
    return v;
}

// ---------------------------------------------------------------------------
// Kernel 1: temporal messages, t-pair per thread (13 loads -> 2 outputs).
// (R9 version verbatim — measured 11.9us, best of tried variants.)
// ---------------------------------------------------------------------------
__global__ __launch_bounds__(256)
void tf_msg(const float* __restrict__ f, const float* __restrict__ s)
{
    const float wt[DWIN + 1] = {
        1.0f, 0.88249690258f, 0.60653065971f, 0.32465246735f, 0.13533528324f,
        0.04393693362f, 0.01110899654f, 0.00218749112f, 3.35462628e-4f,
        4.00652974e-5f, 3.72665317e-6f, 2.69957850e-7f, 1.52299797e-8f };

    const int idx  = blockIdx.x * 256 + threadIdx.x;
    const int pair = idx / 18;
    const int r    = idx - pair * 18;
    const int tp   = pair >> 5;
    const int b    = pair & 31;
    const int t0   = 2 * tp;
    const int n0   = t0 * B_ + b;

    const float* src; int C; int ch; bool past;
    if      (r < 6)  { src = f; C = F_; ch = r * 4;          past = true;  }
    else if (r < 12) { src = f; C = F_; ch = r * 4 - 24;     past = false; }
    else if (r < 15) { src = s; C = S_; ch = (r - 12) * 4;   past = true;  }
    else             { src = s; C = S_; ch = (r - 15) * 4;   past = false; }

    const long stride = (long)B_ * C;
    const float* base = src + (long)n0 * C + ch;

    float4 a0 = make_float4(0.f,0.f,0.f,0.f);
    float4 a1 = make_float4(0.f,0.f,0.f,0.f);
    float sc0, sc1;

    if (past) {
        const bool fast = (t0 >= DWIN);
        #pragma unroll
        for (int j = 0; j <= DWIN; j++) {
            if (fast || t0 - j >= 0) {
                float4 v = *(const float4*)(base - j * stride);
                if (j >= 1)     { a0.x += wt[j]*v.x;   a0.y += wt[j]*v.y;   a0.z += wt[j]*v.z;   a0.w += wt[j]*v.w; }
                if (j <= DWIN-1){ a1.x += wt[j+1]*v.x; a1.y += wt[j+1]*v.y; a1.z += wt[j+1]*v.z; a1.w += wt[j+1]*v.w; }
            }
        }
        sc0 = __frcp_rn(fmaxf((float)t0, 1.0f));
        sc1 = __frcp_rn((float)(t0 + 1));
    } else {
        const bool fast = (t0 <= (L_ - 1) - (DWIN + 1));
        #pragma unroll
        for (int j = 0; j <= DWIN; j++) {
            if (fast || t0 + 1 + j <= L_ - 1) {
                float4 v = *(const float4*)(base + (1 + j) * stride);
                if (j <= DWIN-1){ a0.x += wt[j+1]*v.x; a0.y += wt[j+1]*v.y; a0.z += wt[j+1]*v.z; a0.w += wt[j+1]*v.w; }
                if (j >= 1)     { a1.x += wt[j]*v.x;   a1.y += wt[j]*v.y;   a1.z += wt[j]*v.z;   a1.w += wt[j]*v.w; }
            }
        }
        sc0 = __frcp_rn(fmaxf((float)((L_ - 1) - t0), 1.0f));
        sc1 = __frcp_rn(fmaxf((float)((L_ - 2) - t0), 1.0f));
    }
    a0.x *= sc0; a0.y *= sc0; a0.z *= sc0; a0.w *= sc0;
    a1.x *= sc1; a1.y *= sc1; a1.z *= sc1; a1.w *= sc1;
    *(float4*)(g_msg + (long)n0 * MSGC + r * 4) = a0;
    *(float4*)(g_msg + (long)(n0 + B_) * MSGC + r * 4) = a1;
}

// ---------------------------------------------------------------------------
// Kernel 2: 16 n per CTA, 3-stage cp.async pipeline; per-CTA loss accumulated
// in thread 0; last-finishing CTA reduces all 2048 partials (deterministic).
// ---------------------------------------------------------------------------
struct Chunk { const float4* src; int stride; int dst; };

__device__ __forceinline__ Chunk make_chunk(
    int q, int n0,
    const float* f, const float* s, const float* fs, const float* ff,
    const float* ss, const float* fst, const float* sft)
{
    Chunk c;
    if (q < 144) {
        int j = q;
        c.src = (const float4*)ff + (long)n0 * 144 + j; c.stride = 144;
        c.dst = OFF_FF + (j / 6) * 28 + (j % 6) * 4;
    } else if (q < 216) {
        int j = q - 144;
        c.src = (const float4*)fs + (long)n0 * 72 + j; c.stride = 72;
        c.dst = OFF_FS + (j / 3) * 20 + (j % 3) * 4;
    } else if (q < 288) {
        int j = q - 216;
        c.src = (const float4*)fst + (long)n0 * 72 + j; c.stride = 72;
        c.dst = OFF_FST + (j / 3) * 20 + (j % 3) * 4;
    } else if (q < 360) {
        int j = q - 288;
        c.src = (const float4*)sft + (long)n0 * 72 + j; c.stride = 72;
        c.dst = OFF_SFT + (j / 6) * 28 + (j % 6) * 4;
    } else if (q < 396) {
        int j = q - 360;
        c.src = (const float4*)ss + (long)n0 * 36 + j; c.stride = 36;
        c.dst = OFF_SS + (j / 3) * 20 + (j % 3) * 4;
    } else if (q < 414) {
        int j = q - 396;
        c.src = (const float4*)g_msg + (long)n0 * 18 + j; c.stride = 18;
        c.dst = OFF_MSG + j * 4;
    } else if (q < 420) {
        int j = q - 414;
        c.src = (const float4*)f + (long)n0 * 6 + j; c.stride = 6;
        c.dst = OFF_F + j * 4;
    } else {
        int j = q - 420;
        c.src = (const float4*)s + (long)n0 * 3 + j; c.stride = 3;
        c.dst = OFF_S + j * 4;
    }
    return c;
}

__global__ __launch_bounds__(128)
void tf_main(const float* __restrict__ f, const float* __restrict__ s,
             const float* __restrict__ fs, const float* __restrict__ ff,
             const float* __restrict__ ss, const float* __restrict__ fst,
             const float* __restrict__ sft,
             const int* __restrict__ fl_g, const int* __restrict__ sl_g,
             const int* __restrict__ yl_g,
             const int* __restrict__ y2f, const int* __restrict__ y2s,
             float* __restrict__ out_f, float* __restrict__ out_s,
             float* __restrict__ out_loss)
{
    const int n0  = blockIdx.x * NITER;
    const int tid = threadIdx.x;
    const int lane = tid & 31;
    const int wid = tid >> 5;

    __shared__ __align__(16) float sm[NSTAGE * PN];
    __shared__ float s_sc[2][6];
    __shared__ unsigned int s_rank;

    const uint32_t smb = smem_u32(sm);

    Chunk c0 = make_chunk(tid,       n0, f, s, fs, ff, ss, fst, sft);
    Chunk c1 = make_chunk(tid + 128, n0, f, s, fs, ff, ss, fst, sft);
    Chunk c2 = make_chunk(tid + 256, n0, f, s, fs, ff, ss, fst, sft);
    const bool has3 = (tid + 384) < NCHUNK;
    Chunk c3 = make_chunk(has3 ? tid + 384 : 0, n0, f, s, fs, ff, ss, fst, sft);

    // prefetch iterations 0 and 1 into buffers 0 and 1
    #pragma unroll
    for (int p = 0; p < 2; p++) {
        const uint32_t nb = smb + (uint32_t)(p * PN) * 4;
        cp16(nb + (uint32_t)c0.dst * 4, c0.src); c0.src += c0.stride;
        cp16(nb + (uint32_t)c1.dst * 4, c1.src); c1.src += c1.stride;
        cp16(nb + (uint32_t)c2.dst * 4, c2.src); c2.src += c2.stride;
        if (has3) { cp16(nb + (uint32_t)c3.dst * 4, c3.src); c3.src += c3.stride; }
        cp_commit();
    }

    float loss_acc = 0.0f;      // thread 0 only
    int bi = 0;
    int pi = 2;
    for (int i = 0; i < NITER; i++) {
        const int n = n0 + i;
        const float* base = sm + bi * PN;

        int lab = 0, yidx = 0;
        if (lane == 0) {
            if (wid == 0)      { lab = fl_g[n]; }
            else if (wid == 1) { lab = sl_g[n]; }
            else if (wid == 2) { lab = fl_g[n]; yidx = y2f[yl_g[n]]; }
            else               { lab = sl_g[n]; yidx = y2s[yl_g[n]]; }
        }

        if (i + 1 < NITER) cp_wait<1>(); else cp_wait<0>();
        __syncthreads();
        // all warps past epilogue i-1 -> overwriting buffer pi is race-free

        if (i + 2 < NITER) {
            const uint32_t nb = smb + (uint32_t)(pi * PN) * 4;
            cp16(nb + (uint32_t)c0.dst * 4, c0.src); c0.src += c0.stride;
            cp16(nb + (uint32_t)c1.dst * 4, c1.src); c1.src += c1.stride;
            cp16(nb + (uint32_t)c2.dst * 4, c2.src); c2.src += c2.stride;
            if (has3) { cp16(nb + (uint32_t)c3.dst * 4, c3.src); c3.src += c3.stride; }
            cp_commit();
        }

        // deferred loss combine for iteration i-1
        if (tid == 0 && i > 0) {
            const float* sc = s_sc[(i - 1) & 1];
            loss_acc += -(sc[0] + sc[1] + sc[2] + sc[3]) - sc[4] * sc[5];
        }

        const float* fmp = base + OFF_MSG;
        const float* fmf = base + OFF_MSG + 24;
        const float* smp = base + OFF_MSG + 48;
        const float* smf = base + OFF_MSG + 60;
        const int lab_b  = __shfl_sync(0xffffffffu, lab, 0);
        const int yidx_b = __shfl_sync(0xffffffffu, yidx, 0);
        float* sc = s_sc[i & 1];

        if (wid == 0) {
            float nf = -INFINITY;
            if (lane < F_) {
                const int g = lane;
                float4 ffr[6], fstr[3], fsr[3];
                #pragma unroll
                for (int j = 0; j < 6; j++) ffr[j]  = *(const float4*)(base + OFF_FF  + g*28 + 4*j);
                #pragma unroll
                for (int j = 0; j < 3; j++) fstr[j] = *(const float4*)(base + OFF_FST + g*20 + 4*j);
                #pragma unroll
                for (int j = 0; j < 3; j++) fsr[j]  = *(const float4*)(base + OFF_FS  + g*20 + 4*j);
                float a1 = 0.f, a2 = 0.f, a3 = 0.f, a4 = 0.f, a5 = 0.f;
                #pragma unroll
                for (int k = 0; k < F_; k++) a1 += fmp[k] * base[OFF_FF + k*28 + g];
                #pragma unroll
                for (int k = 0; k < F_; k++) a2 += ((const float*)ffr)[k] * fmf[k];
                #pragma unroll
                for (int k = 0; k < S_; k++) a3 += smp[k] * base[OFF_SFT + k*28 + g];
                #pragma unroll
                for (int k = 0; k < S_; k++) a4 += ((const float*)fstr)[k] * smf[k];
                #pragma unroll
                for (int k = 0; k < S_; k++) a5 += ((const float*)fsr)[k] * base[OFF_S + k];
                nf = base[OFF_F + g] + 0.5f * (((a1 + a2) + (a3 + a4)) + a5);
            }
            float m = warp_max_red(nf);
            float e = (lane < F_) ? __expf(nf - m) : 0.0f;
            float z = warp_sum_red(e);
            float rz = __frcp_rn(z);
            if (lane < F_) out_f[(long)n * F_ + lane] = e * rz;
            float nf_l = __shfl_sync(0xffffffffu, nf, lab_b);
            if (lane == 0) sc[0] = nf_l - (m + __logf(z));
        } else if (wid == 1) {
            float ns = -INFINITY;
            if (lane < S_) {
                const int u = lane;
                float4 ssr[3], sftr[6];
                #pragma unroll
                for (int j = 0; j < 3; j++) ssr[j]  = *(const float4*)(base + OFF_SS  + u*20 + 4*j);
                #pragma unroll
                for (int j = 0; j < 6; j++) sftr[j] = *(const float4*)(base + OFF_SFT + u*28 + 4*j);
                float a1 = 0.f, a2 = 0.f, a3 = 0.f, a4 = 0.f, a5 = 0.f;
                #pragma unroll
                for (int k = 0; k < S_; k++) a1 += smp[k] * base[OFF_SS + k*20 + u];
                #pragma unroll
                for (int k = 0; k < S_; k++) a2 += ((const float*)ssr)[k] * smf[k];
                #pragma unroll
                for (int k = 0; k < F_; k++) a3 += fmp[k] * base[OFF_FST + k*20 + u];
                #pragma unroll
                for (int k = 0; k < F_; k++) a4 += ((const float*)sftr)[k] * fmf[k];
                #pragma unroll
                for (int k = 0; k < F_; k++) a5 += base[OFF_F + k] * base[OFF_FS + k*20 + u];
                ns = base[OFF_S + u] + 0.5f * (((a1 + a2) + (a3 + a4)) + a5);
            }
            float m = warp_max_red(ns);
            float e = (lane < S_) ? __expf(ns - m) : 0.0f;
            float z = warp_sum_red(e);
            float rz = __frcp_rn(z);
            if (lane < S_) out_s[(long)n * S_ + lane] = e * rz;
            float ns_l = __shfl_sync(0xffffffffu, ns, lab_b);
            if (lane == 0) sc[1] = ns_l - (m + __logf(z));
        } else if (wid == 2) {
            float xf = (lane < F_) ? base[OFF_F + lane] : -INFINITY;
            float m = warp_max_red(xf);
            float e = (lane < F_) ? __expf(xf - m) : 0.0f;
            float z = warp_sum_red(e);
            float xf_l = __shfl_sync(0xffffffffu, xf, lab_b);
            float pf_y = __shfl_sync(0xffffffffu, e, yidx_b) * __frcp_rn(z);
            if (lane == 0) { sc[2] = xf_l - (m + __logf(z)); sc[4] = pf_y; }
        } else {
            float xs = (lane < S_) ? base[OFF_S + lane] : -INFINITY;
            float m = warp_max_red(xs);
            float e = (lane < S_) ? __expf(xs - m) : 0.0f;
            float z = warp_sum_red(e);
            float xs_l = __shfl_sync(0xffffffffu, xs, lab_b);
            float ps_y = __shfl_sync(0xffffffffu, e, yidx_b) * __frcp_rn(z);
            if (lane == 0) { sc[3] = xs_l - (m + __logf(z)); sc[5] = ps_y; }
        }

        bi = (bi == NSTAGE - 1) ? 0 : bi + 1;
        pi = (pi == NSTAGE - 1) ? 0 : pi + 1;
    }
    __syncthreads();

    // publish per-CTA loss partial; last-finishing CTA reduces all 2048.
    if (tid == 0) {
        const float* sc = s_sc[(NITER - 1) & 1];
        loss_acc += -(sc[0] + sc[1] + sc[2] + sc[3]) - sc[4] * sc[5];
        g_partial[blockIdx.x] = loss_acc;
        __threadfence();
        s_rank = atomicAdd(&g_done, 1u);
    }
    __syncthreads();
    if (s_rank == NBLK - 1) {
        // deterministic final reduce: fixed order over 512 float4
        __shared__ float sh[128];
        const float4* gp = (const float4*)g_partial;
        float a = 0.0f;
        #pragma unroll
        for (int j = 0; j < 4; j++) {
            float4 v = gp[tid + j * 128];
            a += (v.x + v.y) + (v.z + v.w);
        }
        sh[tid] = a;
        __syncthreads();
        #pragma unroll
        for (int st = 64; st; st >>= 1) {
            if (tid < st) sh[tid] += sh[tid + st];
            __syncthreads();
        }
        if (tid == 0) {
            *out_loss = sh[0] * (1.0f / (float)NN);
            g_done = 0;                 // reset for next graph replay
        }
    }
}

extern "C" void kernel_launch(void* const* d_in, const int* in_sizes, int n_in,
                              void* d_out, int out_size)
{
    const float* f   = (const float*)d_in[0];
    const float* s   = (const float*)d_in[1];
    const float* fs  = (const float*)d_in[2];
    const float* ff  = (const float*)d_in[3];
    const float* ss  = (const float*)d_in[4];
    const float* fst = (const float*)d_in[5];
    const float* sft = (const float*)d_in[6];
    const int*   fl  = (const int*)d_in[7];
    const int*   sl  = (const int*)d_in[8];
    const int*   yl  = (const int*)d_in[9];
    // d_in[10] = mask: all-true by construction; terms reduce to plain means.
    const int*   y2f = (const int*)d_in[11];
    const int*   y2s = (const int*)d_in[12];

    float* out   = (float*)d_out;
    float* out_f = out;
    float* out_s = out + (long)NN * F_;
    float* out_l = out + (long)NN * (F_ + S_);

    tf_msg <<<(NN / 2) * 18 / 256, 256>>>(f, s);
    tf_main<<<NBLK, 128>>>(f, s, fs, ff, ss, fst, sft, fl, sl, yl, y2f, y2s,
                           out_f, out_s, out_l);
}